// round 3
// baseline (speedup 1.0000x reference)
#include <cuda_runtime.h>
#include <cstdint>

// ---------------------------------------------------------------------------
// GroupedLinear: y[b, g*256+o] = sum_i x[b, g*256+i] * W[g,o,i] + bias[g,o]
// 16 independent GEMMs: M=8192, N=256, K=256, fp32 in/out.
//
// R2 was issue-bound (8 warps/SM, tensor 43%, occ 12%, regs 255).
// R3: CTA tile 256x128, 512 threads (16 warps, 4x4 grid, warp tile 64x32,
// 64 acc regs/thread -> <=128 regs, no spill), same 4-stage cp.async pipe.
// ---------------------------------------------------------------------------

namespace gl {

constexpr int INF  = 4096;
constexpr int NG   = 16;
constexpr int GIN  = 256;          // K per group
constexpr int GOUT = 256;          // N per group
constexpr int MT   = 256;          // CTA M tile
constexpr int NT   = 128;          // CTA N tile
constexpr int KCH  = 32;           // K chunk: 32 floats = 128 B rows
constexpr int NCHUNK = GIN / KCH;  // 8
constexpr int STAGES = 4;
constexpr int NTHREADS = 512;      // 16 warps, 4(M) x 4(N) warp grid

constexpr int A_BYTES = MT * KCH * 4;    // 32 KB per stage
constexpr int B_BYTES = NT * KCH * 4;    // 16 KB per stage
constexpr int STAGE_BYTES = A_BYTES + B_BYTES;  // 48 KB

constexpr int OFF_BIAS  = 0;             // 128 floats (CTA's N slice)
constexpr int OFF_STAGE = 1024;
constexpr int SMEM_TOTAL = OFF_STAGE + STAGES * STAGE_BYTES;  // 197632 B

__device__ __forceinline__ uint32_t swz(uint32_t x) {
    return x ^ ((x >> 3) & 0x70);
}

__device__ __forceinline__ void cp16(uint32_t dst, const void* src) {
    asm volatile("cp.async.cg.shared.global [%0], [%1], 16;"
                 :: "r"(dst), "l"(src) : "memory");
}

__device__ __forceinline__ uint32_t smem_u32(const void* p) {
    uint32_t a;
    asm("{ .reg .u64 t; cvta.to.shared.u64 t, %1; cvt.u32.u64 %0, t; }"
        : "=r"(a) : "l"(p));
    return a;
}

// fp32 -> tf32 round-to-nearest
__device__ __forceinline__ uint32_t f2tf(float f) {
    uint32_t r;
    asm("cvt.rna.tf32.f32 %0, %1;" : "=r"(r) : "f"(f));
    return r;
}

__device__ __forceinline__ float lds32(uint32_t addr) {
    float v;
    asm volatile("ld.shared.f32 %0, [%1];" : "=f"(v) : "r"(addr));
    return v;
}

__device__ __forceinline__ void mma_tf32(float* c,
                                         uint32_t a0, uint32_t a1,
                                         uint32_t a2, uint32_t a3,
                                         uint32_t b0, uint32_t b1) {
    asm volatile(
        "mma.sync.aligned.m16n8k8.row.col.f32.tf32.tf32.f32 "
        "{%0,%1,%2,%3}, {%4,%5,%6,%7}, {%8,%9}, {%0,%1,%2,%3};"
        : "+f"(c[0]), "+f"(c[1]), "+f"(c[2]), "+f"(c[3])
        : "r"(a0), "r"(a1), "r"(a2), "r"(a3), "r"(b0), "r"(b1));
}

} // namespace gl

using namespace gl;

__global__ __launch_bounds__(NTHREADS, 1)
void GroupedLinear_35364760715975_kernel(const float* __restrict__ x,
                                         const float* __restrict__ Wt,
                                         const float* __restrict__ bias,
                                         float* __restrict__ y)
{
    extern __shared__ char smem[];
    const uint32_t sbase = smem_u32(smem);
    const int tid = threadIdx.x;

    const int g  = blockIdx.x >> 6;          // group 0..15
    const int r6 = blockIdx.x & 63;
    const int mt = r6 >> 1;                  // m-tile 0..31
    const int nt = r6 & 1;                   // n-tile 0..1
    const int m0 = mt * MT;
    const int n0 = nt * NT;
    const int gbase = g * GIN;

    // bias slice -> smem
    float* sbias = (float*)(smem + OFF_BIAS);
    if (tid < NT) sbias[tid] = bias[g * GOUT + n0 + tid];

    // ---- cooperative stage loader (cp.async, swizzled 128B rows) ----
    const float* xs_base = x + (size_t)m0 * INF + gbase;
    const float* ws_base = Wt + (size_t)g * GOUT * GIN + (size_t)n0 * GIN;

    auto load_stage = [&](int buf, int kt) {
        const uint32_t abase = sbase + OFF_STAGE + buf * STAGE_BYTES;
        const uint32_t bbase = abase + A_BYTES;
        const int kcol = kt * KCH;
        // A: 256 rows x 128B = 2048 x 16B chunks (4 per thread)
        const float* xs = xs_base + kcol;
        #pragma unroll
        for (int i = 0; i < 4; i++) {
            int idx = tid + i * NTHREADS;
            int rr = idx >> 3, ss = idx & 7;
            cp16(abase + swz((uint32_t)(rr * 128 + ss * 16)),
                 xs + (size_t)rr * INF + ss * 4);
        }
        // B: 128 rows x 128B = 1024 x 16B chunks (2 per thread)
        const float* ws = ws_base + kcol;
        #pragma unroll
        for (int i = 0; i < 2; i++) {
            int idx = tid + i * NTHREADS;
            int rr = idx >> 3, ss = idx & 7;
            cp16(bbase + swz((uint32_t)(rr * 128 + ss * 16)),
                 ws + (size_t)rr * GIN + ss * 4);
        }
    };

    // ---- prologue: fill stages 0..2 ----
    load_stage(0, 0); asm volatile("cp.async.commit_group;" ::: "memory");
    load_stage(1, 1); asm volatile("cp.async.commit_group;" ::: "memory");
    load_stage(2, 2); asm volatile("cp.async.commit_group;" ::: "memory");

    // ---- per-warp geometry: 4(M) x 4(N) warps, warp tile 64x32 ----
    const int wid = tid >> 5;
    const int lane = tid & 31;
    const int wm = wid >> 2;          // 0..3
    const int wn = wid & 3;           // 0..3
    const int grp = lane >> 2;        // 0..7
    const int tig = lane & 3;         // 0..3

    float acc[4][4][4];               // [m-tile][n-tile][reg] = 64 regs
    #pragma unroll
    for (int i = 0; i < 4; i++)
        #pragma unroll
        for (int j = 0; j < 4; j++)
            #pragma unroll
            for (int k = 0; k < 4; k++) acc[i][j][k] = 0.f;

    // ---- mainloop: 8 K-chunks, one barrier per iter ----
    #pragma unroll 1
    for (int kc = 0; kc < NCHUNK; kc++) {
        asm volatile("cp.async.wait_group %0;" :: "n"(STAGES - 2) : "memory");
        __syncthreads();   // stage kc visible to all; stage (kc-1) buffer free

        if (kc + STAGES - 1 < NCHUNK) {
            load_stage((kc + STAGES - 1) & (STAGES - 1), kc + STAGES - 1);
            asm volatile("cp.async.commit_group;" ::: "memory");
        } else {
            asm volatile("cp.async.commit_group;" ::: "memory"); // uniform count
        }

        const uint32_t abase = sbase + OFF_STAGE + (kc & (STAGES - 1)) * STAGE_BYTES;
        const uint32_t bbase = abase + A_BYTES;

        #pragma unroll
        for (int kk = 0; kk < 4; kk++) {
            const int kcol = kk * 8;
            const uint32_t c0 = (uint32_t)((kcol + tig) * 4);
            const uint32_t c4 = (uint32_t)((kcol + tig + 4) * 4);

            // A fragments: 4 m16 tiles x 4 regs
            uint32_t af[4][4];
            #pragma unroll
            for (int mti = 0; mti < 4; mti++) {
                const int row = wm * 64 + mti * 16 + grp;
                af[mti][0] = f2tf(lds32(abase + swz((uint32_t)(row * 128) + c0)));
                af[mti][1] = f2tf(lds32(abase + swz((uint32_t)((row + 8) * 128) + c0)));
                af[mti][2] = f2tf(lds32(abase + swz((uint32_t)(row * 128) + c4)));
                af[mti][3] = f2tf(lds32(abase + swz((uint32_t)((row + 8) * 128) + c4)));
            }
            // B fragments: 4 n8 tiles x 2 regs
            uint32_t bf[4][2];
            #pragma unroll
            for (int nti = 0; nti < 4; nti++) {
                const int nrow = wn * 32 + nti * 8 + grp;
                bf[nti][0] = f2tf(lds32(bbase + swz((uint32_t)(nrow * 128) + c0)));
                bf[nti][1] = f2tf(lds32(bbase + swz((uint32_t)(nrow * 128) + c4)));
            }
            // 16 MMAs
            #pragma unroll
            for (int mti = 0; mti < 4; mti++)
                #pragma unroll
                for (int nti = 0; nti < 4; nti++)
                    mma_tf32(acc[mti][nti],
                             af[mti][0], af[mti][1], af[mti][2], af[mti][3],
                             bf[nti][0], bf[nti][1]);
        }
    }

    asm volatile("cp.async.wait_group 0;" ::: "memory");

    // ---- epilogue: bias add + direct STG.64 ----
    #pragma unroll
    for (int mti = 0; mti < 4; mti++) {
        const int row0 = m0 + wm * 64 + mti * 16 + grp;
        float* yr0 = y + (size_t)row0 * INF + gbase + n0;
        float* yr1 = yr0 + (size_t)8 * INF;
        #pragma unroll
        for (int nti = 0; nti < 4; nti++) {
            const int col = wn * 32 + nti * 8 + tig * 2;
            const float b0 = sbias[col];
            const float b1 = sbias[col + 1];
            float2 v0, v1;
            v0.x = acc[mti][nti][0] + b0;
            v0.y = acc[mti][nti][1] + b1;
            v1.x = acc[mti][nti][2] + b0;
            v1.y = acc[mti][nti][3] + b1;
            *(float2*)(yr0 + col) = v0;
            *(float2*)(yr1 + col) = v1;
        }
    }
}

extern "C" void kernel_launch(void* const* d_in, const int* in_sizes, int n_in,
                              void* d_out, int out_size) {
    const float* x  = (const float*)d_in[0];
    const float* Wt = (const float*)d_in[1];
    const float* b  = (const float*)d_in[2];
    float* y = (float*)d_out;

    cudaFuncSetAttribute(GroupedLinear_35364760715975_kernel,
                         cudaFuncAttributeMaxDynamicSharedMemorySize, SMEM_TOTAL);
    dim3 grid(NG * 64);        // 16 groups x (32 m-tiles x 2 n-tiles)
    dim3 block(NTHREADS);
    GroupedLinear_35364760715975_kernel<<<grid, block, SMEM_TOTAL>>>(x, Wt, b, y);
}

// round 4
// speedup vs baseline: 1.3476x; 1.3476x over previous
#include <cuda_runtime.h>
#include <cstdint>

// ---------------------------------------------------------------------------
// GroupedLinear: y[b, g*256+o] = sum_i x[b, g*256+i] * W[g,o,i] + bias[g,o]
// 16 independent GEMMs: M=8192, N=256, K=256, fp32 in/out.
//
// R3 was issue-bound on swizzle address ALU (~10.7 issues/mma, alu 33%).
// R4: hoist swizzled column offsets (lane-invariant!) -> LDS [reg+imm];
// CTA 128x128, 256 thr, 3-stage cp.async (97KB smem), 2 CTAs/SM.
// ---------------------------------------------------------------------------

namespace gl {

constexpr int INF  = 4096;
constexpr int NG   = 16;
constexpr int GIN  = 256;          // K per group
constexpr int GOUT = 256;          // N per group
constexpr int MT   = 128;          // CTA M tile
constexpr int NT   = 128;          // CTA N tile
constexpr int KCH  = 32;           // K chunk: 32 floats = 128 B rows
constexpr int NCHUNK = GIN / KCH;  // 8
constexpr int STAGES = 3;
constexpr int NTHREADS = 256;      // 8 warps, 2(M) x 4(N) warp grid

constexpr int A_BYTES = MT * KCH * 4;           // 16 KB per stage
constexpr int B_BYTES = NT * KCH * 4;           // 16 KB per stage
constexpr int STAGE_BYTES = A_BYTES + B_BYTES;  // 32 KB

constexpr int OFF_BIAS  = 0;            // 128 floats (CTA's N slice)
constexpr int OFF_STAGE = 1024;
constexpr int SMEM_TOTAL = OFF_STAGE + STAGES * STAGE_BYTES;  // 99328 B -> 2 CTA/SM

__device__ __forceinline__ uint32_t swz(uint32_t x) {
    return x ^ ((x >> 3) & 0x70);
}

__device__ __forceinline__ void cp16(uint32_t dst, const void* src) {
    asm volatile("cp.async.cg.shared.global [%0], [%1], 16;"
                 :: "r"(dst), "l"(src) : "memory");
}

__device__ __forceinline__ uint32_t smem_u32(const void* p) {
    uint32_t a;
    asm("{ .reg .u64 t; cvta.to.shared.u64 t, %1; cvt.u32.u64 %0, t; }"
        : "=r"(a) : "l"(p));
    return a;
}

// fp32 -> tf32 round-to-nearest
__device__ __forceinline__ uint32_t f2tf(float f) {
    uint32_t r;
    asm("cvt.rna.tf32.f32 %0, %1;" : "=r"(r) : "f"(f));
    return r;
}

__device__ __forceinline__ float lds32(uint32_t addr) {
    float v;
    asm volatile("ld.shared.f32 %0, [%1];" : "=f"(v) : "r"(addr));
    return v;
}

__device__ __forceinline__ void mma_tf32(float* c,
                                         uint32_t a0, uint32_t a1,
                                         uint32_t a2, uint32_t a3,
                                         uint32_t b0, uint32_t b1) {
    asm volatile(
        "mma.sync.aligned.m16n8k8.row.col.f32.tf32.tf32.f32 "
        "{%0,%1,%2,%3}, {%4,%5,%6,%7}, {%8,%9}, {%0,%1,%2,%3};"
        : "+f"(c[0]), "+f"(c[1]), "+f"(c[2]), "+f"(c[3])
        : "r"(a0), "r"(a1), "r"(a2), "r"(a3), "r"(b0), "r"(b1));
}

} // namespace gl

using namespace gl;

__global__ __launch_bounds__(NTHREADS, 2)
void GroupedLinear_35364760715975_kernel(const float* __restrict__ x,
                                         const float* __restrict__ Wt,
                                         const float* __restrict__ bias,
                                         float* __restrict__ y)
{
    extern __shared__ char smem[];
    const uint32_t sbase = smem_u32(smem);
    const int tid = threadIdx.x;

    const int g   = blockIdx.x >> 7;        // group 0..15
    const int rem = blockIdx.x & 127;
    const int mt  = rem >> 1;               // m-tile 0..63
    const int nt  = rem & 1;                // n-tile 0..1 (adjacent bids share A)
    const int m0 = mt * MT;
    const int n0 = nt * NT;
    const int gbase = g * GIN;

    // bias slice -> smem
    float* sbias = (float*)(smem + OFF_BIAS);
    if (tid < NT) sbias[tid] = bias[g * GOUT + n0 + tid];

    // ---- cooperative stage loader (cp.async, swizzled 128B rows) ----
    const float* xs_base = x + (size_t)m0 * INF + gbase;
    const float* ws_base = Wt + (size_t)g * GOUT * GIN + (size_t)n0 * GIN;

    // per-thread loader geometry (constant across stages)
    const int lrr = tid >> 3;        // row 0..31 step: +32 per i (idx=tid+i*256 -> rr=lrr+32i)
    const int lss = tid & 7;         // 16B slot within 128B row

    auto load_stage = [&](int buf, int kt) {
        const uint32_t abase = sbase + OFF_STAGE + buf * STAGE_BYTES;
        const uint32_t bbase = abase + A_BYTES;
        const int kcol = kt * KCH;
        const float* xs = xs_base + kcol + (size_t)lrr * INF + lss * 4;
        const float* ws = ws_base + kcol + (size_t)lrr * GIN + lss * 4;
        #pragma unroll
        for (int i = 0; i < 4; i++) {
            const int rr = lrr + i * 32;
            cp16(abase + swz((uint32_t)(rr * 128 + lss * 16)),
                 xs + (size_t)(i * 32) * INF);
            cp16(bbase + swz((uint32_t)(rr * 128 + lss * 16)),
                 ws + (size_t)(i * 32) * GIN);
        }
    };

    // ---- prologue: fill stages 0..1 ----
    load_stage(0, 0); asm volatile("cp.async.commit_group;" ::: "memory");
    load_stage(1, 1); asm volatile("cp.async.commit_group;" ::: "memory");

    // ---- per-warp geometry: 2(M) x 4(N) warps, warp tile 64x32 ----
    const int wid = tid >> 5;
    const int lane = tid & 31;
    const int wm = wid >> 2;          // 0..1
    const int wn = wid & 3;           // 0..3
    const int grp = lane >> 2;        // 0..7 (== fragment row & 7 for ALL tiles)
    const int tig = lane & 3;         // 0..3

    // Hoisted swizzled column offsets: for any fragment row, row&7 == grp, so
    // swz(row*128 + c) == row*128 + (c ^ (grp<<4)).  Loop-invariant per lane.
    uint32_t colA[4];
    #pragma unroll
    for (int kk = 0; kk < 4; kk++)
        colA[kk] = (uint32_t)((kk * 8 + tig) * 4) ^ (uint32_t)(grp << 4);
    const uint32_t aWarpOff = (uint32_t)(wm << 13) + (uint32_t)(grp << 7); // wm*8192 + grp*128
    const uint32_t bWarpOff = (uint32_t)(wn << 12) + (uint32_t)(grp << 7); // wn*4096 + grp*128

    float acc[4][4][4];               // [m-tile][n-tile][reg] = 64 regs
    #pragma unroll
    for (int i = 0; i < 4; i++)
        #pragma unroll
        for (int j = 0; j < 4; j++)
            #pragma unroll
            for (int k = 0; k < 4; k++) acc[i][j][k] = 0.f;

    // ---- mainloop: 8 K-chunks ----
    #pragma unroll 1
    for (int kc = 0; kc < NCHUNK; kc++) {
        asm volatile("cp.async.wait_group 1;" ::: "memory");
        __syncthreads();   // stage kc visible; stage buffer (kc+2)%3 free

        if (kc + STAGES - 1 < NCHUNK) {
            load_stage((kc + STAGES - 1) % STAGES, kc + STAGES - 1);
            asm volatile("cp.async.commit_group;" ::: "memory");
        } else {
            asm volatile("cp.async.commit_group;" ::: "memory"); // uniform count
        }

        const uint32_t abase = sbase + OFF_STAGE + (kc % STAGES) * STAGE_BYTES;
        const uint32_t Abase = abase + aWarpOff;
        const uint32_t Bbase = abase + A_BYTES + bWarpOff;

        #pragma unroll
        for (int kk = 0; kk < 4; kk++) {
            const uint32_t a0 = Abase + colA[kk];   // bit4 of Abase is 0 -> ^16 ok
            const uint32_t a4 = a0 ^ 16u;
            const uint32_t b0 = Bbase + colA[kk];
            const uint32_t b4 = b0 ^ 16u;

            // A fragments: 4 m16 tiles x 4 regs, all [reg + imm]
            uint32_t af[4][4];
            #pragma unroll
            for (int mti = 0; mti < 4; mti++) {
                af[mti][0] = f2tf(lds32(a0 + mti * 2048));
                af[mti][1] = f2tf(lds32(a0 + mti * 2048 + 1024));
                af[mti][2] = f2tf(lds32(a4 + mti * 2048));
                af[mti][3] = f2tf(lds32(a4 + mti * 2048 + 1024));
            }
            // B fragments: 4 n8 tiles x 2 regs
            uint32_t bf[4][2];
            #pragma unroll
            for (int nti = 0; nti < 4; nti++) {
                bf[nti][0] = f2tf(lds32(b0 + nti * 1024));
                bf[nti][1] = f2tf(lds32(b4 + nti * 1024));
            }
            // 16 MMAs
            #pragma unroll
            for (int mti = 0; mti < 4; mti++)
                #pragma unroll
                for (int nti = 0; nti < 4; nti++)
                    mma_tf32(acc[mti][nti],
                             af[mti][0], af[mti][1], af[mti][2], af[mti][3],
                             bf[nti][0], bf[nti][1]);
        }
    }

    asm volatile("cp.async.wait_group 0;" ::: "memory");

    // ---- epilogue: bias add + direct STG.64 ----
    #pragma unroll
    for (int mti = 0; mti < 4; mti++) {
        const int row0 = m0 + wm * 64 + mti * 16 + grp;
        float* yr0 = y + (size_t)row0 * INF + gbase + n0;
        float* yr1 = yr0 + (size_t)8 * INF;
        #pragma unroll
        for (int nti = 0; nti < 4; nti++) {
            const int col = wn * 32 + nti * 8 + tig * 2;
            const float b0 = sbias[col];
            const float b1 = sbias[col + 1];
            float2 v0, v1;
            v0.x = acc[mti][nti][0] + b0;
            v0.y = acc[mti][nti][1] + b1;
            v1.x = acc[mti][nti][2] + b0;
            v1.y = acc[mti][nti][3] + b1;
            *(float2*)(yr0 + col) = v0;
            *(float2*)(yr1 + col) = v1;
        }
    }
}

extern "C" void kernel_launch(void* const* d_in, const int* in_sizes, int n_in,
                              void* d_out, int out_size) {
    const float* x  = (const float*)d_in[0];
    const float* Wt = (const float*)d_in[1];
    const float* b  = (const float*)d_in[2];
    float* y = (float*)d_out;

    cudaFuncSetAttribute(GroupedLinear_35364760715975_kernel,
                         cudaFuncAttributeMaxDynamicSharedMemorySize, SMEM_TOTAL);
    dim3 grid(NG * 128);       // 16 groups x (64 m-tiles x 2 n-tiles) = 2048 CTAs
    dim3 block(NTHREADS);
    GroupedLinear_35364760715975_kernel<<<grid, block, SMEM_TOTAL>>>(x, Wt, b, y);
}

// round 5
// speedup vs baseline: 1.4441x; 1.0716x over previous
#include <cuda_runtime.h>
#include <cstdint>

// ---------------------------------------------------------------------------
// GroupedLinear: y[b, g*256+o] = sum_i x[b, g*256+i] * W[g,o,i] + bias[g,o]
// 16 independent GEMMs: M=8192, N=256, K=256, fp32 in/out.
//
// R4: 119us, tensor 48%, mma.sync-tf32 math floor ~57us.
// R5: ldmatrix.x4 (b16 trick on 32-bit tf32 data) replaces 24 scalar LDS per
// k8-step with 6 LDSM; warp-staggered k-step order breaks the post-barrier
// LDS convoy. CTA 128x128, 256 thr, 3-stage cp.async, 2 CTAs/SM.
// ---------------------------------------------------------------------------

namespace gl {

constexpr int INF  = 4096;
constexpr int NG   = 16;
constexpr int GIN  = 256;          // K per group
constexpr int GOUT = 256;          // N per group
constexpr int MT   = 128;          // CTA M tile
constexpr int NT   = 128;          // CTA N tile
constexpr int KCH  = 32;           // K chunk: 32 floats = 128 B rows
constexpr int NCHUNK = GIN / KCH;  // 8
constexpr int STAGES = 3;
constexpr int NTHREADS = 256;      // 8 warps, 2(M) x 4(N) warp grid

constexpr int A_BYTES = MT * KCH * 4;           // 16 KB per stage
constexpr int B_BYTES = NT * KCH * 4;           // 16 KB per stage
constexpr int STAGE_BYTES = A_BYTES + B_BYTES;  // 32 KB

constexpr int OFF_BIAS  = 0;            // 128 floats (CTA's N slice)
constexpr int OFF_STAGE = 1024;
constexpr int SMEM_TOTAL = OFF_STAGE + STAGES * STAGE_BYTES;  // 99328 B -> 2 CTA/SM

__device__ __forceinline__ uint32_t swz(uint32_t x) {
    return x ^ ((x >> 3) & 0x70);
}

__device__ __forceinline__ void cp16(uint32_t dst, const void* src) {
    asm volatile("cp.async.cg.shared.global [%0], [%1], 16;"
                 :: "r"(dst), "l"(src) : "memory");
}

__device__ __forceinline__ uint32_t smem_u32(const void* p) {
    uint32_t a;
    asm("{ .reg .u64 t; cvta.to.shared.u64 t, %1; cvt.u32.u64 %0, t; }"
        : "=r"(a) : "l"(p));
    return a;
}

// fp32 -> tf32 round-to-nearest
__device__ __forceinline__ uint32_t f2tf(uint32_t fbits) {
    uint32_t r;
    asm("cvt.rna.tf32.f32 %0, %1;" : "=r"(r) : "r"(fbits));
    return r;
}

// ldmatrix x4 on 32-bit data: each m8n8.b16 matrix = one 8x4 fp32 quadrant;
// thread T receives fp32 element (row = T/4, col = T%4) of each quadrant.
__device__ __forceinline__ void ldsm4(uint32_t& r0, uint32_t& r1,
                                      uint32_t& r2, uint32_t& r3,
                                      uint32_t addr) {
    asm volatile("ldmatrix.sync.aligned.m8n8.x4.shared.b16 {%0,%1,%2,%3}, [%4];"
                 : "=r"(r0), "=r"(r1), "=r"(r2), "=r"(r3) : "r"(addr));
}

__device__ __forceinline__ void mma_tf32(float* c,
                                         uint32_t a0, uint32_t a1,
                                         uint32_t a2, uint32_t a3,
                                         uint32_t b0, uint32_t b1) {
    asm volatile(
        "mma.sync.aligned.m16n8k8.row.col.f32.tf32.tf32.f32 "
        "{%0,%1,%2,%3}, {%4,%5,%6,%7}, {%8,%9}, {%0,%1,%2,%3};"
        : "+f"(c[0]), "+f"(c[1]), "+f"(c[2]), "+f"(c[3])
        : "r"(a0), "r"(a1), "r"(a2), "r"(a3), "r"(b0), "r"(b1));
}

} // namespace gl

using namespace gl;

__global__ __launch_bounds__(NTHREADS, 2)
void GroupedLinear_35364760715975_kernel(const float* __restrict__ x,
                                         const float* __restrict__ Wt,
                                         const float* __restrict__ bias,
                                         float* __restrict__ y)
{
    extern __shared__ char smem[];
    const uint32_t sbase = smem_u32(smem);
    const int tid = threadIdx.x;

    const int g   = blockIdx.x >> 7;        // group 0..15
    const int rem = blockIdx.x & 127;
    const int mt  = rem >> 1;               // m-tile 0..63
    const int nt  = rem & 1;                // n-tile 0..1
    const int m0 = mt * MT;
    const int n0 = nt * NT;
    const int gbase = g * GIN;

    // bias slice -> smem
    float* sbias = (float*)(smem + OFF_BIAS);
    if (tid < NT) sbias[tid] = bias[g * GOUT + n0 + tid];

    // ---- cooperative stage loader (cp.async, swizzled 128B rows) ----
    const float* xs_base = x + (size_t)m0 * INF + gbase;
    const float* ws_base = Wt + (size_t)g * GOUT * GIN + (size_t)n0 * GIN;

    const int lrr = tid >> 3;        // row 0..31, +32 per i
    const int lss = tid & 7;         // 16B slot within 128B row

    auto load_stage = [&](int buf, int kt) {
        const uint32_t abase = sbase + OFF_STAGE + buf * STAGE_BYTES;
        const uint32_t bbase = abase + A_BYTES;
        const int kcol = kt * KCH;
        const float* xs = xs_base + kcol + (size_t)lrr * INF + lss * 4;
        const float* ws = ws_base + kcol + (size_t)lrr * GIN + lss * 4;
        #pragma unroll
        for (int i = 0; i < 4; i++) {
            const int rr = lrr + i * 32;
            cp16(abase + swz((uint32_t)(rr * 128 + lss * 16)),
                 xs + (size_t)(i * 32) * INF);
            cp16(bbase + swz((uint32_t)(rr * 128 + lss * 16)),
                 ws + (size_t)(i * 32) * GIN);
        }
    };

    // ---- prologue: fill stages 0..1 ----
    load_stage(0, 0); asm volatile("cp.async.commit_group;" ::: "memory");
    load_stage(1, 1); asm volatile("cp.async.commit_group;" ::: "memory");

    // ---- per-warp geometry: 2(M) x 4(N) warps, warp tile 64x32 ----
    const int wid  = tid >> 5;
    const int lane = tid & 31;
    const int wm = wid >> 2;          // 0..1
    const int wn = wid & 3;           // 0..3
    const int grp = lane >> 2;        // 0..7
    const int tig = lane & 3;         // 0..3
    const int kk0 = wid & 3;          // stagger k-step start per warp

    // ldmatrix lane geometry: q = quadrant group, i = row within quadrant
    const int q = lane >> 3;          // 0..3
    const int i8 = lane & 7;          // 0..7
    const uint32_t ix = (uint32_t)i8 << 4;
    // A: q&1 selects row-half (m +8), q>>1 selects k-half (+16B)
    const uint32_t aq16 = (uint32_t)((q >> 1) << 4);
    const uint32_t arow = (uint32_t)(((q & 1) * 8 + i8) * 128) + (uint32_t)(wm << 13);
    // B: q>>1 selects n-half (+8 rows), q&1 selects k-half (+16B)
    const uint32_t bq16 = (uint32_t)((q & 1) << 4);
    const uint32_t brow = (uint32_t)(((q >> 1) * 8 + i8) * 128) + (uint32_t)(wn << 12);

    float acc[4][4][4];               // [m-tile][n-tile][reg] = 64 regs
    #pragma unroll
    for (int a = 0; a < 4; a++)
        #pragma unroll
        for (int b = 0; b < 4; b++)
            #pragma unroll
            for (int c = 0; c < 4; c++) acc[a][b][c] = 0.f;

    // ---- mainloop: 8 K-chunks ----
    #pragma unroll 1
    for (int kc = 0; kc < NCHUNK; kc++) {
        asm volatile("cp.async.wait_group 1;" ::: "memory");
        __syncthreads();   // stage kc visible; stage buffer (kc+2)%3 free

        if (kc + STAGES - 1 < NCHUNK) {
            load_stage((kc + STAGES - 1) % STAGES, kc + STAGES - 1);
            asm volatile("cp.async.commit_group;" ::: "memory");
        } else {
            asm volatile("cp.async.commit_group;" ::: "memory"); // uniform count
        }

        const uint32_t stage = sbase + OFF_STAGE + (kc % STAGES) * STAGE_BYTES;
        const uint32_t Arow = stage + arow;
        const uint32_t Brow = stage + A_BYTES + brow;

        #pragma unroll
        for (int j = 0; j < 4; j++) {
            const int kk = (j + kk0) & 3;
            const uint32_t cxA = ((uint32_t)(kk * 32) + aq16) ^ ix;
            const uint32_t cxB = ((uint32_t)(kk * 32) + bq16) ^ ix;

            // A fragments: 4 m16 tiles, one ldmatrix.x4 each
            uint32_t af[4][4];
            #pragma unroll
            for (int mti = 0; mti < 4; mti++)
                ldsm4(af[mti][0], af[mti][1], af[mti][2], af[mti][3],
                      Arow + (uint32_t)(mti * 2048) + cxA);

            // B fragments: 4 n8 tiles, two ldmatrix.x4
            uint32_t bf[4][2];
            ldsm4(bf[0][0], bf[0][1], bf[1][0], bf[1][1], Brow + cxB);
            ldsm4(bf[2][0], bf[2][1], bf[3][0], bf[3][1], Brow + 2048u + cxB);

            // round to tf32 (rna)
            #pragma unroll
            for (int mti = 0; mti < 4; mti++)
                #pragma unroll
                for (int r = 0; r < 4; r++) af[mti][r] = f2tf(af[mti][r]);
            #pragma unroll
            for (int nti = 0; nti < 4; nti++) {
                bf[nti][0] = f2tf(bf[nti][0]);
                bf[nti][1] = f2tf(bf[nti][1]);
            }

            // 16 MMAs
            #pragma unroll
            for (int mti = 0; mti < 4; mti++)
                #pragma unroll
                for (int nti = 0; nti < 4; nti++)
                    mma_tf32(acc[mti][nti],
                             af[mti][0], af[mti][1], af[mti][2], af[mti][3],
                             bf[nti][0], bf[nti][1]);
        }
    }

    asm volatile("cp.async.wait_group 0;" ::: "memory");

    // ---- epilogue: bias add + direct STG.64 ----
    #pragma unroll
    for (int mti = 0; mti < 4; mti++) {
        const int row0 = m0 + wm * 64 + mti * 16 + grp;
        float* yr0 = y + (size_t)row0 * INF + gbase + n0;
        float* yr1 = yr0 + (size_t)8 * INF;
        #pragma unroll
        for (int nti = 0; nti < 4; nti++) {
            const int col = wn * 32 + nti * 8 + tig * 2;
            const float b0 = sbias[col];
            const float b1 = sbias[col + 1];
            float2 v0, v1;
            v0.x = acc[mti][nti][0] + b0;
            v0.y = acc[mti][nti][1] + b1;
            v1.x = acc[mti][nti][2] + b0;
            v1.y = acc[mti][nti][3] + b1;
            *(float2*)(yr0 + col) = v0;
            *(float2*)(yr1 + col) = v1;
        }
    }
}

extern "C" void kernel_launch(void* const* d_in, const int* in_sizes, int n_in,
                              void* d_out, int out_size) {
    const float* x  = (const float*)d_in[0];
    const float* Wt = (const float*)d_in[1];
    const float* b  = (const float*)d_in[2];
    float* y = (float*)d_out;

    cudaFuncSetAttribute(GroupedLinear_35364760715975_kernel,
                         cudaFuncAttributeMaxDynamicSharedMemorySize, SMEM_TOTAL);
    dim3 grid(NG * 128);       // 16 groups x (64 m-tiles x 2 n-tiles) = 2048 CTAs
    dim3 block(NTHREADS);
    GroupedLinear_35364760715975_kernel<<<grid, block, SMEM_TOTAL>>>(x, Wt, b, y);
}

// round 6
// speedup vs baseline: 1.5985x; 1.1069x over previous
#include <cuda_runtime.h>
#include <cstdint>

// ---------------------------------------------------------------------------
// GroupedLinear: y[b, g*256+o] = sum_i x[b, g*256+i] * W[g,o,i] + bias[g,o]
// 16 independent GEMMs: M=8192, N=256, K=256, fp32 in/out.
//
// R5: 111us, tensor 52%. Binder = 24 in-loop cvt.rna.tf32 per 16 MMA.
// R6: W pre-rounded to tf32 once into __device__ scratch (prologue kernel);
// A uses HW tf32 truncation (no in-loop cvt at all). Issue mix per k8-step
// drops 50 -> 26 slots per 16 MMA. Loader dst swizzle offsets hoisted.
// ---------------------------------------------------------------------------

namespace gl {

constexpr int INF  = 4096;
constexpr int NG   = 16;
constexpr int GIN  = 256;          // K per group
constexpr int GOUT = 256;          // N per group
constexpr int MT   = 128;          // CTA M tile
constexpr int NT   = 128;          // CTA N tile
constexpr int KCH  = 32;           // K chunk: 32 floats = 128 B rows
constexpr int NCHUNK = GIN / KCH;  // 8
constexpr int STAGES = 3;
constexpr int NTHREADS = 256;      // 8 warps, 2(M) x 4(N) warp grid

constexpr int A_BYTES = MT * KCH * 4;           // 16 KB per stage
constexpr int B_BYTES = NT * KCH * 4;           // 16 KB per stage
constexpr int STAGE_BYTES = A_BYTES + B_BYTES;  // 32 KB

constexpr int OFF_BIAS  = 0;            // 128 floats (CTA's N slice)
constexpr int OFF_STAGE = 1024;
constexpr int SMEM_TOTAL = OFF_STAGE + STAGES * STAGE_BYTES;  // 99328 B -> 2 CTA/SM

__device__ __forceinline__ uint32_t swz(uint32_t x) {
    return x ^ ((x >> 3) & 0x70);
}

__device__ __forceinline__ void cp16(uint32_t dst, const void* src) {
    asm volatile("cp.async.cg.shared.global [%0], [%1], 16;"
                 :: "r"(dst), "l"(src) : "memory");
}

__device__ __forceinline__ uint32_t smem_u32(const void* p) {
    uint32_t a;
    asm("{ .reg .u64 t; cvta.to.shared.u64 t, %1; cvt.u32.u64 %0, t; }"
        : "=r"(a) : "l"(p));
    return a;
}

// fp32 -> tf32 round-to-nearest (used only in the W prologue kernel)
__device__ __forceinline__ float f2tf_f(float f) {
    uint32_t r;
    asm("cvt.rna.tf32.f32 %0, %1;" : "=r"(r) : "f"(f));
    return __uint_as_float(r);
}

// ldmatrix x4 on 32-bit data: each m8n8.b16 matrix = one 8x4 fp32 quadrant;
// thread T receives fp32 element (row = T/4, col = T%4) of each quadrant.
__device__ __forceinline__ void ldsm4(uint32_t& r0, uint32_t& r1,
                                      uint32_t& r2, uint32_t& r3,
                                      uint32_t addr) {
    asm volatile("ldmatrix.sync.aligned.m8n8.x4.shared.b16 {%0,%1,%2,%3}, [%4];"
                 : "=r"(r0), "=r"(r1), "=r"(r2), "=r"(r3) : "r"(addr));
}

__device__ __forceinline__ void mma_tf32(float* c,
                                         uint32_t a0, uint32_t a1,
                                         uint32_t a2, uint32_t a3,
                                         uint32_t b0, uint32_t b1) {
    asm volatile(
        "mma.sync.aligned.m16n8k8.row.col.f32.tf32.tf32.f32 "
        "{%0,%1,%2,%3}, {%4,%5,%6,%7}, {%8,%9}, {%0,%1,%2,%3};"
        : "+f"(c[0]), "+f"(c[1]), "+f"(c[2]), "+f"(c[3])
        : "r"(a0), "r"(a1), "r"(a2), "r"(a3), "r"(b0), "r"(b1));
}

} // namespace gl

using namespace gl;

// 4MB scratch: W rounded to tf32 once per launch (idempotent, deterministic).
__device__ float g_Wr[NG * GOUT * GIN];

__global__ __launch_bounds__(256, 4)
void GroupedLinear_roundW_kernel(const float4* __restrict__ W) {
    const int i = blockIdx.x * 256 + threadIdx.x;   // 1024 blocks -> 262144 float4
    float4 v = W[i];
    v.x = f2tf_f(v.x);
    v.y = f2tf_f(v.y);
    v.z = f2tf_f(v.z);
    v.w = f2tf_f(v.w);
    reinterpret_cast<float4*>(g_Wr)[i] = v;
}

__global__ __launch_bounds__(NTHREADS, 2)
void GroupedLinear_35364760715975_kernel(const float* __restrict__ x,
                                         const float* __restrict__ bias,
                                         float* __restrict__ y)
{
    extern __shared__ char smem[];
    const uint32_t sbase = smem_u32(smem);
    const int tid = threadIdx.x;

    const int g   = blockIdx.x >> 7;        // group 0..15
    const int rem = blockIdx.x & 127;
    const int mt  = rem >> 1;               // m-tile 0..63
    const int nt  = rem & 1;                // n-tile 0..1
    const int m0 = mt * MT;
    const int n0 = nt * NT;
    const int gbase = g * GIN;

    // bias slice -> smem
    float* sbias = (float*)(smem + OFF_BIAS);
    if (tid < NT) sbias[tid] = bias[g * GOUT + n0 + tid];

    // ---- cooperative stage loader (cp.async, swizzled 128B rows) ----
    const int lrr = tid >> 3;        // row 0..31, +32 per i
    const int lss = tid & 7;         // 16B slot within 128B row

    // hoisted per-thread pointers & swizzled dst offsets
    const float* xs0 = x + (size_t)(m0 + lrr) * INF + gbase + lss * 4;
    const float* ws0 = g_Wr + (size_t)g * GOUT * GIN + (size_t)(n0 + lrr) * GIN + lss * 4;
    uint32_t dsto[4];
    #pragma unroll
    for (int i = 0; i < 4; i++)
        dsto[i] = swz((uint32_t)((lrr + i * 32) * 128 + lss * 16));

    auto load_stage = [&](int buf, int kt) {
        const uint32_t abase = sbase + OFF_STAGE + buf * STAGE_BYTES;
        const uint32_t bbase = abase + A_BYTES;
        const float* xs = xs0 + kt * KCH;
        const float* ws = ws0 + kt * KCH;
        #pragma unroll
        for (int i = 0; i < 4; i++) {
            cp16(abase + dsto[i], xs + (size_t)(i * 32) * INF);
            cp16(bbase + dsto[i], ws + (size_t)(i * 32) * GIN);
        }
    };

    // ---- prologue: fill stages 0..1 ----
    load_stage(0, 0); asm volatile("cp.async.commit_group;" ::: "memory");
    load_stage(1, 1); asm volatile("cp.async.commit_group;" ::: "memory");

    // ---- per-warp geometry: 2(M) x 4(N) warps, warp tile 64x32 ----
    const int wid  = tid >> 5;
    const int lane = tid & 31;
    const int wm = wid >> 2;          // 0..1
    const int wn = wid & 3;           // 0..3
    const int grp = lane >> 2;        // 0..7
    const int tig = lane & 3;         // 0..3
    const int kk0 = wid & 3;          // stagger k-step start per warp

    // ldmatrix lane geometry
    const int q = lane >> 3;          // 0..3
    const int i8 = lane & 7;          // 0..7
    const uint32_t ix = (uint32_t)i8 << 4;
    const uint32_t aq16 = (uint32_t)((q >> 1) << 4);
    const uint32_t arow = (uint32_t)(((q & 1) * 8 + i8) * 128) + (uint32_t)(wm << 13);
    const uint32_t bq16 = (uint32_t)((q & 1) << 4);
    const uint32_t brow = (uint32_t)(((q >> 1) * 8 + i8) * 128) + (uint32_t)(wn << 12);

    float acc[4][4][4];               // [m-tile][n-tile][reg] = 64 regs
    #pragma unroll
    for (int a = 0; a < 4; a++)
        #pragma unroll
        for (int b = 0; b < 4; b++)
            #pragma unroll
            for (int c = 0; c < 4; c++) acc[a][b][c] = 0.f;

    // ---- mainloop: 8 K-chunks ----
    #pragma unroll 1
    for (int kc = 0; kc < NCHUNK; kc++) {
        asm volatile("cp.async.wait_group 1;" ::: "memory");
        __syncthreads();   // stage kc visible; stage buffer (kc+2)%3 free

        if (kc + STAGES - 1 < NCHUNK) {
            load_stage((kc + STAGES - 1) % STAGES, kc + STAGES - 1);
            asm volatile("cp.async.commit_group;" ::: "memory");
        } else {
            asm volatile("cp.async.commit_group;" ::: "memory"); // uniform count
        }

        const uint32_t stage = sbase + OFF_STAGE + (kc % STAGES) * STAGE_BYTES;
        const uint32_t Arow = stage + arow;
        const uint32_t Brow = stage + A_BYTES + brow;

        #pragma unroll
        for (int j = 0; j < 4; j++) {
            const int kk = (j + kk0) & 3;
            const uint32_t cxA = ((uint32_t)(kk * 32) + aq16) ^ ix;
            const uint32_t cxB = ((uint32_t)(kk * 32) + bq16) ^ ix;

            // A fragments: raw fp32 bits (HW truncates to tf32)
            uint32_t af[4][4];
            #pragma unroll
            for (int mti = 0; mti < 4; mti++)
                ldsm4(af[mti][0], af[mti][1], af[mti][2], af[mti][3],
                      Arow + (uint32_t)(mti * 2048) + cxA);

            // B fragments: already tf32-rounded in g_Wr, use directly
            uint32_t bf[4][2];
            ldsm4(bf[0][0], bf[0][1], bf[1][0], bf[1][1], Brow + cxB);
            ldsm4(bf[2][0], bf[2][1], bf[3][0], bf[3][1], Brow + 2048u + cxB);

            // 16 MMAs
            #pragma unroll
            for (int mti = 0; mti < 4; mti++)
                #pragma unroll
                for (int nti = 0; nti < 4; nti++)
                    mma_tf32(acc[mti][nti],
                             af[mti][0], af[mti][1], af[mti][2], af[mti][3],
                             bf[nti][0], bf[nti][1]);
        }
    }

    asm volatile("cp.async.wait_group 0;" ::: "memory");

    // ---- epilogue: bias add + direct STG.64 ----
    #pragma unroll
    for (int mti = 0; mti < 4; mti++) {
        const int row0 = m0 + wm * 64 + mti * 16 + grp;
        float* yr0 = y + (size_t)row0 * INF + gbase + n0;
        float* yr1 = yr0 + (size_t)8 * INF;
        #pragma unroll
        for (int nti = 0; nti < 4; nti++) {
            const int col = wn * 32 + nti * 8 + tig * 2;
            const float b0 = sbias[col];
            const float b1 = sbias[col + 1];
            float2 v0, v1;
            v0.x = acc[mti][nti][0] + b0;
            v0.y = acc[mti][nti][1] + b1;
            v1.x = acc[mti][nti][2] + b0;
            v1.y = acc[mti][nti][3] + b1;
            *(float2*)(yr0 + col) = v0;
            *(float2*)(yr1 + col) = v1;
        }
    }
}

extern "C" void kernel_launch(void* const* d_in, const int* in_sizes, int n_in,
                              void* d_out, int out_size) {
    const float* x  = (const float*)d_in[0];
    const float* Wt = (const float*)d_in[1];
    const float* b  = (const float*)d_in[2];
    float* y = (float*)d_out;

    cudaFuncSetAttribute(GroupedLinear_35364760715975_kernel,
                         cudaFuncAttributeMaxDynamicSharedMemorySize, SMEM_TOTAL);

    // 1) round W -> tf32 scratch (1M floats, 1024 x 256 x float4)
    GroupedLinear_roundW_kernel<<<1024, 256>>>((const float4*)Wt);

    // 2) main GEMM
    dim3 grid(NG * 128);       // 16 groups x (64 m-tiles x 2 n-tiles) = 2048 CTAs
    dim3 block(NTHREADS);
    GroupedLinear_35364760715975_kernel<<<grid, block, SMEM_TOTAL>>>(x, b, y);
}

// round 7
// speedup vs baseline: 1.6338x; 1.0221x over previous
#include <cuda_runtime.h>
#include <cstdint>

// ---------------------------------------------------------------------------
// GroupedLinear: y[b, g*256+o] = sum_i x[b, g*256+i] * W[g,o,i] + bias[g,o]
// 16 independent GEMMs: M=8192, N=256, K=256, fp32 in/out.
//
// R6: 95us main, tensor 59%, L1 62% -> smem BW co-binder (250 B/mma).
// R7: warp tile 64x64 (4 warps/CTA, 128 thr) cuts smem to 187 B/mma; smem
// stops binding, tensor pipe becomes sole limiter. Still 2 CTAs/SM.
// W pre-rounded to tf32 scratch; A uses HW tf32 truncation (no in-loop cvt).
// ---------------------------------------------------------------------------

namespace gl {

constexpr int INF  = 4096;
constexpr int NG   = 16;
constexpr int GIN  = 256;          // K per group
constexpr int GOUT = 256;          // N per group
constexpr int MT   = 128;          // CTA M tile
constexpr int NT   = 128;          // CTA N tile
constexpr int KCH  = 32;           // K chunk: 32 floats = 128 B rows
constexpr int NCHUNK = GIN / KCH;  // 8
constexpr int STAGES = 3;
constexpr int NTHREADS = 128;      // 4 warps, 2(M) x 2(N) grid, warp tile 64x64

constexpr int A_BYTES = MT * KCH * 4;           // 16 KB per stage
constexpr int B_BYTES = NT * KCH * 4;           // 16 KB per stage
constexpr int STAGE_BYTES = A_BYTES + B_BYTES;  // 32 KB

constexpr int OFF_BIAS  = 0;            // 128 floats (CTA's N slice)
constexpr int OFF_STAGE = 1024;
constexpr int SMEM_TOTAL = OFF_STAGE + STAGES * STAGE_BYTES;  // 99328 B -> 2 CTA/SM

__device__ __forceinline__ uint32_t swz(uint32_t x) {
    return x ^ ((x >> 3) & 0x70);
}

__device__ __forceinline__ void cp16(uint32_t dst, const void* src) {
    asm volatile("cp.async.cg.shared.global [%0], [%1], 16;"
                 :: "r"(dst), "l"(src) : "memory");
}

__device__ __forceinline__ uint32_t smem_u32(const void* p) {
    uint32_t a;
    asm("{ .reg .u64 t; cvta.to.shared.u64 t, %1; cvt.u32.u64 %0, t; }"
        : "=r"(a) : "l"(p));
    return a;
}

// fp32 -> tf32 round-to-nearest (used only in the W prologue kernel)
__device__ __forceinline__ float f2tf_f(float f) {
    uint32_t r;
    asm("cvt.rna.tf32.f32 %0, %1;" : "=r"(r) : "f"(f));
    return __uint_as_float(r);
}

// ldmatrix x4 on 32-bit data: each m8n8.b16 matrix = one 8x4 fp32 quadrant;
// thread T receives fp32 element (row = T/4, col = T%4) of each quadrant.
__device__ __forceinline__ void ldsm4(uint32_t& r0, uint32_t& r1,
                                      uint32_t& r2, uint32_t& r3,
                                      uint32_t addr) {
    asm volatile("ldmatrix.sync.aligned.m8n8.x4.shared.b16 {%0,%1,%2,%3}, [%4];"
                 : "=r"(r0), "=r"(r1), "=r"(r2), "=r"(r3) : "r"(addr));
}

__device__ __forceinline__ void mma_tf32(float* c,
                                         uint32_t a0, uint32_t a1,
                                         uint32_t a2, uint32_t a3,
                                         uint32_t b0, uint32_t b1) {
    asm volatile(
        "mma.sync.aligned.m16n8k8.row.col.f32.tf32.tf32.f32 "
        "{%0,%1,%2,%3}, {%4,%5,%6,%7}, {%8,%9}, {%0,%1,%2,%3};"
        : "+f"(c[0]), "+f"(c[1]), "+f"(c[2]), "+f"(c[3])
        : "r"(a0), "r"(a1), "r"(a2), "r"(a3), "r"(b0), "r"(b1));
}

} // namespace gl

using namespace gl;

// 4MB scratch: W rounded to tf32 once per launch (idempotent, deterministic).
__device__ float g_Wr[NG * GOUT * GIN];

__global__ __launch_bounds__(256, 4)
void GroupedLinear_roundW_kernel(const float4* __restrict__ W) {
    const int i = blockIdx.x * 256 + threadIdx.x;   // 1024 blocks -> 262144 float4
    float4 v = W[i];
    v.x = f2tf_f(v.x);
    v.y = f2tf_f(v.y);
    v.z = f2tf_f(v.z);
    v.w = f2tf_f(v.w);
    reinterpret_cast<float4*>(g_Wr)[i] = v;
}

__global__ __launch_bounds__(NTHREADS, 2)
void GroupedLinear_35364760715975_kernel(const float* __restrict__ x,
                                         const float* __restrict__ bias,
                                         float* __restrict__ y)
{
    extern __shared__ char smem[];
    const uint32_t sbase = smem_u32(smem);
    const int tid = threadIdx.x;

    const int g   = blockIdx.x >> 7;        // group 0..15
    const int rem = blockIdx.x & 127;
    const int mt  = rem >> 1;               // m-tile 0..63
    const int nt  = rem & 1;                // n-tile 0..1
    const int m0 = mt * MT;
    const int n0 = nt * NT;
    const int gbase = g * GIN;

    // bias slice -> smem
    float* sbias = (float*)(smem + OFF_BIAS);
    if (tid < NT) sbias[tid] = bias[g * GOUT + n0 + tid];

    // ---- cooperative stage loader (cp.async, swizzled 128B rows) ----
    const int lrr = tid >> 3;        // row 0..15, +16 per i
    const int lss = tid & 7;         // 16B slot within 128B row

    const float* xs0 = x + (size_t)(m0 + lrr) * INF + gbase + lss * 4;
    const float* ws0 = g_Wr + (size_t)g * GOUT * GIN + (size_t)(n0 + lrr) * GIN + lss * 4;
    uint32_t dsto[8];
    #pragma unroll
    for (int i = 0; i < 8; i++)
        dsto[i] = swz((uint32_t)((lrr + i * 16) * 128 + lss * 16));

    auto load_stage = [&](int buf, int kt) {
        const uint32_t abase = sbase + OFF_STAGE + buf * STAGE_BYTES;
        const uint32_t bbase = abase + A_BYTES;
        const float* xs = xs0 + kt * KCH;
        const float* ws = ws0 + kt * KCH;
        #pragma unroll
        for (int i = 0; i < 8; i++) {
            cp16(abase + dsto[i], xs + (size_t)(i * 16) * INF);
            cp16(bbase + dsto[i], ws + (size_t)(i * 16) * GIN);
        }
    };

    // ---- prologue: fill stages 0..1 ----
    load_stage(0, 0); asm volatile("cp.async.commit_group;" ::: "memory");
    load_stage(1, 1); asm volatile("cp.async.commit_group;" ::: "memory");

    // ---- per-warp geometry: 2(M) x 2(N) warps, warp tile 64x64 ----
    const int wid  = tid >> 5;
    const int lane = tid & 31;
    const int wm = wid >> 1;          // 0..1
    const int wn = wid & 1;           // 0..1
    const int grp = lane >> 2;        // 0..7
    const int tig = lane & 3;         // 0..3
    const int kk0 = wid & 3;          // stagger k-step start per warp

    // ldmatrix lane geometry
    const int q = lane >> 3;          // 0..3
    const int i8 = lane & 7;          // 0..7
    const uint32_t ix = (uint32_t)i8 << 4;
    const uint32_t aq16 = (uint32_t)((q >> 1) << 4);
    const uint32_t arow = (uint32_t)(((q & 1) * 8 + i8) * 128) + (uint32_t)(wm << 13);
    const uint32_t bq16 = (uint32_t)((q & 1) << 4);
    const uint32_t brow = (uint32_t)(((q >> 1) * 8 + i8) * 128) + (uint32_t)(wn << 13);

    float acc[4][8][4];               // [m16-tile][n8-tile][reg] = 128 regs
    #pragma unroll
    for (int a = 0; a < 4; a++)
        #pragma unroll
        for (int b = 0; b < 8; b++)
            #pragma unroll
            for (int c = 0; c < 4; c++) acc[a][b][c] = 0.f;

    // ---- mainloop: 8 K-chunks ----
    #pragma unroll 1
    for (int kc = 0; kc < NCHUNK; kc++) {
        asm volatile("cp.async.wait_group 1;" ::: "memory");
        __syncthreads();   // stage kc visible; stage buffer (kc+2)%3 free

        if (kc + STAGES - 1 < NCHUNK) {
            load_stage((kc + STAGES - 1) % STAGES, kc + STAGES - 1);
            asm volatile("cp.async.commit_group;" ::: "memory");
        } else {
            asm volatile("cp.async.commit_group;" ::: "memory"); // uniform count
        }

        const uint32_t stage = sbase + OFF_STAGE + (kc % STAGES) * STAGE_BYTES;
        const uint32_t Arow = stage + arow;
        const uint32_t Brow = stage + A_BYTES + brow;

        #pragma unroll
        for (int j = 0; j < 4; j++) {
            const int kk = (j + kk0) & 3;
            const uint32_t cxA = ((uint32_t)(kk * 32) + aq16) ^ ix;
            const uint32_t cxB = ((uint32_t)(kk * 32) + bq16) ^ ix;

            // A fragments: 4 m16 tiles, raw fp32 bits (HW truncates to tf32)
            uint32_t af[4][4];
            #pragma unroll
            for (int mti = 0; mti < 4; mti++)
                ldsm4(af[mti][0], af[mti][1], af[mti][2], af[mti][3],
                      Arow + (uint32_t)(mti * 2048) + cxA);

            // B fragments: 8 n8 tiles (pre-rounded tf32), 4 ldmatrix.x4
            uint32_t bf[8][2];
            #pragma unroll
            for (int nt2 = 0; nt2 < 4; nt2++)
                ldsm4(bf[2 * nt2][0], bf[2 * nt2][1],
                      bf[2 * nt2 + 1][0], bf[2 * nt2 + 1][1],
                      Brow + (uint32_t)(nt2 * 2048) + cxB);

            // 32 MMAs
            #pragma unroll
            for (int mti = 0; mti < 4; mti++)
                #pragma unroll
                for (int nti = 0; nti < 8; nti++)
                    mma_tf32(acc[mti][nti],
                             af[mti][0], af[mti][1], af[mti][2], af[mti][3],
                             bf[nti][0], bf[nti][1]);
        }
    }

    asm volatile("cp.async.wait_group 0;" ::: "memory");

    // ---- epilogue: bias add + direct STG.64 ----
    #pragma unroll
    for (int mti = 0; mti < 4; mti++) {
        const int row0 = m0 + wm * 64 + mti * 16 + grp;
        float* yr0 = y + (size_t)row0 * INF + gbase + n0;
        float* yr1 = yr0 + (size_t)8 * INF;
        #pragma unroll
        for (int nti = 0; nti < 8; nti++) {
            const int col = wn * 64 + nti * 8 + tig * 2;
            const float b0 = sbias[col];
            const float b1 = sbias[col + 1];
            float2 v0, v1;
            v0.x = acc[mti][nti][0] + b0;
            v0.y = acc[mti][nti][1] + b1;
            v1.x = acc[mti][nti][2] + b0;
            v1.y = acc[mti][nti][3] + b1;
            *(float2*)(yr0 + col) = v0;
            *(float2*)(yr1 + col) = v1;
        }
    }
}

extern "C" void kernel_launch(void* const* d_in, const int* in_sizes, int n_in,
                              void* d_out, int out_size) {
    const float* x  = (const float*)d_in[0];
    const float* Wt = (const float*)d_in[1];
    const float* b  = (const float*)d_in[2];
    float* y = (float*)d_out;

    cudaFuncSetAttribute(GroupedLinear_35364760715975_kernel,
                         cudaFuncAttributeMaxDynamicSharedMemorySize, SMEM_TOTAL);

    // 1) round W -> tf32 scratch (1M floats, 1024 x 256 x float4)
    GroupedLinear_roundW_kernel<<<1024, 256>>>((const float4*)Wt);

    // 2) main GEMM
    dim3 grid(NG * 128);       // 16 groups x (64 m-tiles x 2 n-tiles) = 2048 CTAs
    dim3 block(NTHREADS);
    GroupedLinear_35364760715975_kernel<<<grid, block, SMEM_TOTAL>>>(x, b, y);
}

// round 8
// speedup vs baseline: 1.6614x; 1.0169x over previous
#include <cuda_runtime.h>
#include <cstdint>

// ---------------------------------------------------------------------------
// GroupedLinear: y[b, g*256+o] = sum_i x[b, g*256+i] * W[g,o,i] + bias[g,o]
// 16 independent GEMMs: M=8192, N=256, K=256, fp32 in/out.
//
// R7: 94.5us main, tensor 60%, issue 19% -> binder is per-CTA serial
// overhead (prologue fill, epilogue, wave transitions), not smem/issue.
// R8: persistent CTAs (grid=304=2x152SM), continuous cp.async pipeline
// across tile boundaries, epilogue inline between chunks, bias from global.
// W pre-rounded to tf32 scratch; A uses HW tf32 truncation.
// ---------------------------------------------------------------------------

namespace gl {

constexpr int INF  = 4096;
constexpr int NG   = 16;
constexpr int GIN  = 256;          // K per group
constexpr int GOUT = 256;          // N per group
constexpr int MT   = 128;          // CTA M tile
constexpr int NT   = 128;          // CTA N tile
constexpr int KCH  = 32;           // K chunk: 32 floats = 128 B rows
constexpr int NCHUNK = 8;          // K chunks per tile
constexpr int TILES = 2048;        // 16 groups x 64 m-tiles x 2 n-tiles
constexpr int NCTA  = 304;         // 2 CTAs x 152 SMs (GB300)
constexpr int STAGES = 3;
constexpr int NTHREADS = 128;      // 4 warps, 2(M) x 2(N), warp tile 64x64

constexpr int A_BYTES = MT * KCH * 4;           // 16 KB per stage
constexpr int B_BYTES = NT * KCH * 4;           // 16 KB per stage
constexpr int STAGE_BYTES = A_BYTES + B_BYTES;  // 32 KB

constexpr int OFF_STAGE = 1024;
constexpr int SMEM_TOTAL = OFF_STAGE + STAGES * STAGE_BYTES;  // 99328 B -> 2 CTA/SM

__device__ __forceinline__ uint32_t swz(uint32_t x) {
    return x ^ ((x >> 3) & 0x70);
}

__device__ __forceinline__ void cp16(uint32_t dst, const void* src) {
    asm volatile("cp.async.cg.shared.global [%0], [%1], 16;"
                 :: "r"(dst), "l"(src) : "memory");
}

__device__ __forceinline__ uint32_t smem_u32(const void* p) {
    uint32_t a;
    asm("{ .reg .u64 t; cvta.to.shared.u64 t, %1; cvt.u32.u64 %0, t; }"
        : "=r"(a) : "l"(p));
    return a;
}

// fp32 -> tf32 round-to-nearest (used only in the W prologue kernel)
__device__ __forceinline__ float f2tf_f(float f) {
    uint32_t r;
    asm("cvt.rna.tf32.f32 %0, %1;" : "=r"(r) : "f"(f));
    return __uint_as_float(r);
}

// ldmatrix x4 on 32-bit data: each m8n8.b16 matrix = one 8x4 fp32 quadrant;
// thread T receives fp32 element (row = T/4, col = T%4) of each quadrant.
__device__ __forceinline__ void ldsm4(uint32_t& r0, uint32_t& r1,
                                      uint32_t& r2, uint32_t& r3,
                                      uint32_t addr) {
    asm volatile("ldmatrix.sync.aligned.m8n8.x4.shared.b16 {%0,%1,%2,%3}, [%4];"
                 : "=r"(r0), "=r"(r1), "=r"(r2), "=r"(r3) : "r"(addr));
}

__device__ __forceinline__ void mma_tf32(float* c,
                                         uint32_t a0, uint32_t a1,
                                         uint32_t a2, uint32_t a3,
                                         uint32_t b0, uint32_t b1) {
    asm volatile(
        "mma.sync.aligned.m16n8k8.row.col.f32.tf32.tf32.f32 "
        "{%0,%1,%2,%3}, {%4,%5,%6,%7}, {%8,%9}, {%0,%1,%2,%3};"
        : "+f"(c[0]), "+f"(c[1]), "+f"(c[2]), "+f"(c[3])
        : "r"(a0), "r"(a1), "r"(a2), "r"(a3), "r"(b0), "r"(b1));
}

} // namespace gl

using namespace gl;

// 4MB scratch: W rounded to tf32 once per launch (idempotent, deterministic).
__device__ float g_Wr[NG * GOUT * GIN];

__global__ __launch_bounds__(256, 4)
void GroupedLinear_roundW_kernel(const float4* __restrict__ W) {
    const int i = blockIdx.x * 256 + threadIdx.x;   // 1024 blocks -> 262144 float4
    float4 v = W[i];
    v.x = f2tf_f(v.x);
    v.y = f2tf_f(v.y);
    v.z = f2tf_f(v.z);
    v.w = f2tf_f(v.w);
    reinterpret_cast<float4*>(g_Wr)[i] = v;
}

__global__ __launch_bounds__(NTHREADS, 2)
void GroupedLinear_35364760715975_kernel(const float* __restrict__ x,
                                         const float* __restrict__ bias,
                                         float* __restrict__ y)
{
    extern __shared__ char smem[];
    const uint32_t sbase = smem_u32(smem);
    const int tid = threadIdx.x;
    const int bid = blockIdx.x;

    // ---- loader geometry (per thread, constant) ----
    const int lrr = tid >> 3;        // row 0..15, +16 per i
    const int lss = tid & 7;         // 16B slot within 128B row
    uint32_t dsto[8];
    #pragma unroll
    for (int i = 0; i < 8; i++)
        dsto[i] = swz((uint32_t)((lrr + i * 16) * 128 + lss * 16));

    // global chunk index q -> (tile, chunk) -> cp.async into buffer buf
    auto load_stage = [&](int q, int buf) {
        const int t    = q >> 3;
        const int kc   = q & 7;
        const int tile = bid + t * NCTA;
        const int g    = tile >> 7;
        const int rem  = tile & 127;
        const int mt   = rem >> 1;
        const int ntl  = rem & 1;
        const float* xs = x + (size_t)(mt * MT + lrr) * INF
                            + g * GIN + kc * KCH + lss * 4;
        const float* ws = g_Wr + (size_t)g * GOUT * GIN
                               + (size_t)(ntl * NT + lrr) * GIN + kc * KCH + lss * 4;
        const uint32_t abase = sbase + OFF_STAGE + buf * STAGE_BYTES;
        const uint32_t bbase = abase + A_BYTES;
        #pragma unroll
        for (int i = 0; i < 8; i++) {
            cp16(abase + dsto[i], xs + (size_t)(i * 16) * INF);
            cp16(bbase + dsto[i], ws + (size_t)(i * 16) * GIN);
        }
    };

    // tiles for this CTA: bid, bid+NCTA, ...
    const int ntiles = (TILES - 1 - bid) / NCTA + 1;
    const int qtot = ntiles * NCHUNK;

    // ---- prologue: fill 2 stages once ----
    load_stage(0, 0); asm volatile("cp.async.commit_group;" ::: "memory");
    load_stage(1, 1); asm volatile("cp.async.commit_group;" ::: "memory");

    // ---- per-warp geometry: 2(M) x 2(N) warps, warp tile 64x64 ----
    const int wid  = tid >> 5;
    const int lane = tid & 31;
    const int wm = wid >> 1;          // 0..1
    const int wn = wid & 1;           // 0..1
    const int grp = lane >> 2;        // 0..7
    const int tig = lane & 3;         // 0..3
    const int kk0 = wid & 3;          // stagger k-step start per warp

    // ldmatrix lane geometry
    const int q8 = lane >> 3;         // 0..3
    const int i8 = lane & 7;          // 0..7
    const uint32_t ix = (uint32_t)i8 << 4;
    const uint32_t aq16 = (uint32_t)((q8 >> 1) << 4);
    const uint32_t arow = (uint32_t)(((q8 & 1) * 8 + i8) * 128) + (uint32_t)(wm << 13);
    const uint32_t bq16 = (uint32_t)((q8 & 1) << 4);
    const uint32_t brow = (uint32_t)(((q8 >> 1) * 8 + i8) * 128) + (uint32_t)(wn << 13);

    float acc[4][8][4];               // [m16-tile][n8-tile][reg] = 128 regs
    #pragma unroll
    for (int a = 0; a < 4; a++)
        #pragma unroll
        for (int b = 0; b < 8; b++)
            #pragma unroll
            for (int c = 0; c < 4; c++) acc[a][b][c] = 0.f;

    // ---- flat persistent mainloop over (tile, chunk) ----
    int buf = 0, bufn = 2;            // q % 3, (q+2) % 3
    #pragma unroll 1
    for (int q = 0; q < qtot; q++) {
        asm volatile("cp.async.wait_group 1;" ::: "memory");
        __syncthreads();   // stage q visible; buffer (q+2)%3 free

        if (q + 2 < qtot) {
            load_stage(q + 2, bufn);
            asm volatile("cp.async.commit_group;" ::: "memory");
        } else {
            asm volatile("cp.async.commit_group;" ::: "memory"); // uniform count
        }

        const uint32_t stage = sbase + OFF_STAGE + buf * STAGE_BYTES;
        const uint32_t Arow = stage + arow;
        const uint32_t Brow = stage + A_BYTES + brow;

        #pragma unroll
        for (int j = 0; j < 4; j++) {
            const int kk = (j + kk0) & 3;
            const uint32_t cxA = ((uint32_t)(kk * 32) + aq16) ^ ix;
            const uint32_t cxB = ((uint32_t)(kk * 32) + bq16) ^ ix;

            // A fragments: raw fp32 bits (HW truncates to tf32)
            uint32_t af[4][4];
            #pragma unroll
            for (int mti = 0; mti < 4; mti++)
                ldsm4(af[mti][0], af[mti][1], af[mti][2], af[mti][3],
                      Arow + (uint32_t)(mti * 2048) + cxA);

            // B fragments: 8 n8 tiles (pre-rounded tf32)
            uint32_t bf[8][2];
            #pragma unroll
            for (int nt2 = 0; nt2 < 4; nt2++)
                ldsm4(bf[2 * nt2][0], bf[2 * nt2][1],
                      bf[2 * nt2 + 1][0], bf[2 * nt2 + 1][1],
                      Brow + (uint32_t)(nt2 * 2048) + cxB);

            // 32 MMAs
            #pragma unroll
            for (int mti = 0; mti < 4; mti++)
                #pragma unroll
                for (int nti = 0; nti < 8; nti++)
                    mma_tf32(acc[mti][nti],
                             af[mti][0], af[mti][1], af[mti][2], af[mti][3],
                             bf[nti][0], bf[nti][1]);
        }

        // ---- tile boundary: inline epilogue (no sync needed; per-warp data) ----
        if ((q & 7) == 7) {
            const int tile = bid + (q >> 3) * NCTA;
            const int g    = tile >> 7;
            const int rem  = tile & 127;
            const int m0   = (rem >> 1) * MT;
            const int n0   = (rem & 1) * NT;
            const int gb   = g * GIN;

            const float* bp = bias + g * GOUT + n0 + wn * 64 + tig * 2;
            float2 bv[8];
            #pragma unroll
            for (int nti = 0; nti < 8; nti++)
                bv[nti] = *(const float2*)(bp + nti * 8);

            #pragma unroll
            for (int mti = 0; mti < 4; mti++) {
                const int row0 = m0 + wm * 64 + mti * 16 + grp;
                float* yr0 = y + (size_t)row0 * INF + gb + n0 + wn * 64 + tig * 2;
                float* yr1 = yr0 + (size_t)8 * INF;
                #pragma unroll
                for (int nti = 0; nti < 8; nti++) {
                    float2 v0, v1;
                    v0.x = acc[mti][nti][0] + bv[nti].x;
                    v0.y = acc[mti][nti][1] + bv[nti].y;
                    v1.x = acc[mti][nti][2] + bv[nti].x;
                    v1.y = acc[mti][nti][3] + bv[nti].y;
                    *(float2*)(yr0 + nti * 8) = v0;
                    *(float2*)(yr1 + nti * 8) = v1;
                    acc[mti][nti][0] = 0.f; acc[mti][nti][1] = 0.f;
                    acc[mti][nti][2] = 0.f; acc[mti][nti][3] = 0.f;
                }
            }
        }

        buf  = (buf  == 2) ? 0 : buf + 1;
        bufn = (bufn == 2) ? 0 : bufn + 1;
    }
}

extern "C" void kernel_launch(void* const* d_in, const int* in_sizes, int n_in,
                              void* d_out, int out_size) {
    const float* x  = (const float*)d_in[0];
    const float* Wt = (const float*)d_in[1];
    const float* b  = (const float*)d_in[2];
    float* y = (float*)d_out;

    cudaFuncSetAttribute(GroupedLinear_35364760715975_kernel,
                         cudaFuncAttributeMaxDynamicSharedMemorySize, SMEM_TOTAL);

    // 1) round W -> tf32 scratch (1M floats, 1024 x 256 x float4)
    GroupedLinear_roundW_kernel<<<1024, 256>>>((const float4*)Wt);

    // 2) persistent main GEMM: 304 CTAs (2 per SM on 152-SM GB300)
    GroupedLinear_35364760715975_kernel<<<NCTA, NTHREADS, SMEM_TOTAL>>>(x, b, y);
}